// round 16
// baseline (speedup 1.0000x reference)
#include <cuda_runtime.h>
#include <cuda_fp16.h>
#include <math.h>
#include <stdint.h>

// Problem constants
#define BB   8
#define TT   10
#define HH   64
#define WW   64
#define HID  64
#define PRED 10
#define PIX  (HH*WW)              // 4096
#define NST  (BB*HID*PIX)
#define TROW 66
#define TSZ  ((size_t)BB*TROW*TROW*HID)   // elems of one transposed fp16 tensor
#define WSZ  (9*256*64)           // fp16 weights per tensor
#define WBSZ (64*4096*8)          // packed Wc+bias per cell: [co][px][wc0..3,b0..3]

// ---------------------------------------------------------------------------
// Static scratch
// ---------------------------------------------------------------------------
__device__ float g_c[4][NST];                                   // c states
__device__ __align__(16) __half g_T[4][2 * BB*TROW*TROW*HID];   // h, ping-pong
__device__ __align__(16) __half g_W[7][WSZ];
__device__ __align__(16) __half g_WB[4][WBSZ];                  // packed Wc|bias

// ---------------------------------------------------------------------------
// Weight transform: w (256,64,3,3) -> wt[tap][m][k] fp16, m = co*4 + g.
// ---------------------------------------------------------------------------
__global__ void wsplit_kernel(const float* w0, const float* w1, const float* w2,
                              const float* w3, const float* w4, const float* w5,
                              const float* w6, __half* __restrict__ wt_base)
{
    int i = blockIdx.x * blockDim.x + threadIdx.x;
    if (i >= WSZ) return;
    int z = blockIdx.z;
    const float* w;
    switch (z) {
        case 0: w = w0; break;  case 1: w = w1; break;
        case 2: w = w2; break;  case 3: w = w3; break;
        case 4: w = w4; break;  case 5: w = w5; break;
        default: w = w6; break;
    }
    __half* wt = wt_base + (size_t)z * WSZ;
    int c   = i & 63;
    int m   = (i >> 6) & 255;
    int tap = i >> 14;
    int co = m >> 2, g = m & 3;
    wt[i] = __float2half_rn(w[((g * 64 + co) * 64 + c) * 9 + tap]);
}

// ---------------------------------------------------------------------------
// Pack Wc + bias -> [co][px][wc0..3,b0..3] fp16 (one LDG.128 in epilogue)
// ---------------------------------------------------------------------------
__global__ void wcpack_kernel(const float* wc0, const float* b0,
                              const float* wc1, const float* b1,
                              const float* wc2, const float* b2,
                              const float* wc3, const float* b3,
                              __half* __restrict__ out_base)
{
    int i = blockIdx.x * blockDim.x + threadIdx.x;   // over 64*4096
    if (i >= 64 * 4096) return;
    int z = blockIdx.z;
    const float *wc, *bi;
    switch (z) {
        case 0: wc = wc0; bi = b0; break;
        case 1: wc = wc1; bi = b1; break;
        case 2: wc = wc2; bi = b2; break;
        default: wc = wc3; bi = b3; break;
    }
    __half* out = out_base + (size_t)z * WBSZ;
    int px = i & 4095;
    int co = i >> 12;
    __half* dst = out + (size_t)i * 8;
    #pragma unroll
    for (int g = 0; g < 4; g++) {
        dst[g]     = __float2half_rn(wc[(g * 64 + co) * 4096 + px]);
        dst[4 + g] = __float2half_rn(bi[(g * 64 + co) * 4096 + px]);
    }
}

// ---------------------------------------------------------------------------
// low-level helpers
// ---------------------------------------------------------------------------
__device__ __forceinline__ uint32_t smem_u32(const void* p) {
    uint32_t a;
    asm("{ .reg .u64 t; cvta.to.shared.u64 t, %1; cvt.u32.u64 %0, t; }" : "=r"(a) : "l"(p));
    return a;
}
__device__ __forceinline__ void cp16(uint32_t dst, const void* src) {
    asm volatile("cp.async.cg.shared.global [%0], [%1], 16;" :: "r"(dst), "l"(src));
}
#define CP_COMMIT() asm volatile("cp.async.commit_group;" ::: "memory")
#define CP_WAIT0()  asm volatile("cp.async.wait_group 0;" ::: "memory")

__device__ __forceinline__ void ldm_x4(unsigned* r, uint32_t addr) {
    asm volatile("ldmatrix.sync.aligned.m8n8.x4.shared.b16 {%0,%1,%2,%3}, [%4];"
        : "=r"(r[0]), "=r"(r[1]), "=r"(r[2]), "=r"(r[3]) : "r"(addr));
}
__device__ __forceinline__ void mma16816(float* d, const unsigned* a,
                                         unsigned b0, unsigned b1)
{
    asm("mma.sync.aligned.m16n8k16.row.col.f32.f16.f16.f32 "
        "{%0,%1,%2,%3}, {%4,%5,%6,%7}, {%8,%9}, {%0,%1,%2,%3};"
        : "+f"(d[0]), "+f"(d[1]), "+f"(d[2]), "+f"(d[3])
        : "r"(a[0]), "r"(a[1]), "r"(a[2]), "r"(a[3]), "r"(b0), "r"(b1));
}

// Fast activations (EX2/RCP)
__device__ __forceinline__ float ex2f(float x) {
    float r; asm("ex2.approx.f32 %0, %1;" : "=f"(r) : "f"(x)); return r;
}
__device__ __forceinline__ float rcpf(float x) {
    float r; asm("rcp.approx.f32 %0, %1;" : "=f"(r) : "f"(x)); return r;
}
#define LOG2E 1.4426950408889634f
__device__ __forceinline__ float sigf(float v) {
    return rcpf(1.f + ex2f(-v * LOG2E));
}
__device__ __forceinline__ float tanhf_fast(float v) {
    return 1.f - 2.f * rcpf(1.f + ex2f(2.f * LOG2E * v));
}

// SMEM layout (bytes), 512-thread CTA, 2 CTAs/SM (= 32 warps/SM):
//   A tiles: 2 bufs x 64 rows x 144B = 18432   [0 .. 18432)
//   B tile : 396 rows x 144B         = 57024   [18432 .. 75456)
//   Epilogue OVERLAYS the A+B region (all mma reads done by then):
//     sE: 64 gate-rows x 264 f32 = 67584       [0 .. 67584)
//     sH: 256 px x 24 fp16 = 12288             [67584 .. 79872)
#define SA_OFF   0
#define SA_BUF   9216
#define SB_OFF   18432
#define SH_OFF   67584
#define SM_TOTAL 79872
#define ESTR     264
#define HSTR     24

// ---------------------------------------------------------------------------
// Work descriptor
// ---------------------------------------------------------------------------
struct CellArgs {
    const __half* T0;
    const __half* W0;
    const __half* T1;
    const __half* W1;
    int nsrc;
    const __half* wcb;
    const float*  fw;
    const float*  fb;
    float*        cbuf;
    __half*       Tout;
    const float*  xp;
    const float*  wx9;
    int t;
    int kind;           // 0 = cell, 1 = final conv, 2 = none
};

// ---------------------------------------------------------------------------
// Cell body. CTA: M=64 gate-rows (mt 0..3 -> channels mt*16..mt*16+15),
// N=256 px (4 image rows of one batch). 16 warps: wm {0,1} x wn {0..7};
// warp tile 32m x 32n. 2 CTAs/SM (32 warps).
// ---------------------------------------------------------------------------
__device__ __forceinline__ void cell_body(const CellArgs& A, char* smc)
{
    const uint32_t smb = smem_u32(smc);
    float*  sE = (float*)smc;
    __half* sH = (__half*)(smc + SH_OFF);

    const int tid  = threadIdx.x;
    const int lane = tid & 31;
    const int warp = tid >> 5;
    const int wm   = warp >> 3;      // 0..1 (m half: wm*32)
    const int wn   = warp & 7;       // 0..7
    const int nt   = blockIdx.x;     // 0..127
    const int mt   = blockIdx.y;     // 0..3
    const int b    = nt >> 4;
    const int y0   = (nt & 15) << 2; // first of 4 image rows

    const int a_row_l = lane & 15;
    const int a_col_l = (lane >> 4) * 8;
    const int b_row_l = (lane & 7) + ((lane >> 4) << 3);
    const int b_col_l = ((lane >> 3) & 1) * 8;

    float acc[2][4][4];
    #pragma unroll
    for (int mi = 0; mi < 2; mi++)
        #pragma unroll
        for (int ni = 0; ni < 4; ni++)
            #pragma unroll
            for (int r = 0; r < 4; r++) acc[mi][ni][r] = 0.f;

    for (int s = 0; s < A.nsrc; s++) {
        const __half* T = s ? A.T1 : A.T0;
        const __half* W = s ? A.W1 : A.W0;

        __syncthreads();
        // fill B: 396 padded rows (6 x 66) x 8 vec16
        for (int i = tid; i < 3168; i += 512) {
            int p = i >> 3, v = i & 7;
            int r = p / TROW, px = p - r * TROW;
            const __half* src =
                T + (((size_t)b * TROW + (y0 + r)) * TROW + px) * 64 + v * 8;
            cp16(smb + SB_OFF + p * 144 + v * 16, src);
        }
        // fill A tap0: 64 rows x 8 vec16 (one per thread)
        {
            int m = tid >> 3, v = tid & 7;
            const __half* src = W + (mt * 64 + m) * 64 + v * 8;
            cp16(smb + SA_OFF + m * 144 + v * 16, src);
        }
        CP_COMMIT();

        for (int tap = 0; tap < 9; tap++) {
            CP_WAIT0();
            __syncthreads();
            if (tap < 8) {
                const int nb = (tap + 1) & 1;
                int m = tid >> 3, v = tid & 7;
                const __half* src = W + (tap + 1) * 16384 + (mt * 64 + m) * 64 + v * 8;
                cp16(smb + SA_OFF + nb * SA_BUF + m * 144 + v * 16, src);
                CP_COMMIT();
            }

            const int dy = tap / 3, dx = tap - dy * 3;
            const int ylocal = wn >> 1, xlocal = (wn & 1) * 32;
            const int prow_base = (ylocal + dy) * TROW + xlocal + dx;
            const uint32_t aBase = smb + SA_OFF + (tap & 1) * SA_BUF;
            const uint32_t bBase = smb + SB_OFF;

            #pragma unroll
            for (int ks = 0; ks < 4; ks++) {
                unsigned bfr[2][4];
                #pragma unroll
                for (int p2 = 0; p2 < 2; p2++)
                    ldm_x4(bfr[p2], bBase + (prow_base + p2 * 16 + b_row_l) * 144
                                          + (ks * 16 + b_col_l) * 2);
                unsigned afr[2][4];
                #pragma unroll
                for (int mi = 0; mi < 2; mi++)
                    ldm_x4(afr[mi], aBase + (wm * 32 + mi * 16 + a_row_l) * 144
                                          + (a_col_l + ks * 16) * 2);
                #pragma unroll
                for (int p2 = 0; p2 < 2; p2++)
                    #pragma unroll
                    for (int mi = 0; mi < 2; mi++) {
                        mma16816(acc[mi][2 * p2],     afr[mi], bfr[p2][0], bfr[p2][1]);
                        mma16816(acc[mi][2 * p2 + 1], afr[mi], bfr[p2][2], bfr[p2][3]);
                    }
            }
        }
    }

    // ---- epilogue (sE and sH overlay the A+B region; mma is done) ----
    __syncthreads();
    const int gr = lane >> 2, ci = lane & 3;
    #pragma unroll
    for (int mi = 0; mi < 2; mi++)
        #pragma unroll
        for (int ni = 0; ni < 4; ni++) {
            int r0 = wm * 32 + mi * 16 + gr;
            int n  = wn * 32 + ni * 8 + 2 * ci;
            *(float2*)(sE + r0 * ESTR + n)       = make_float2(acc[mi][ni][0], acc[mi][ni][1]);
            *(float2*)(sE + (r0 + 8) * ESTR + n) = make_float2(acc[mi][ni][2], acc[mi][ni][3]);
        }
    __syncthreads();

    {
        const int pl    = tid & 255;          // pixel 0..255
        const int chalf = tid >> 8;           // 0..1 -> cols chalf*8 .. +7
        const int pix   = y0 * 64 + pl;
        float xv[9];
        if (A.xp) {
            int y = pix >> 6, xx = pix & 63;
            #pragma unroll
            for (int tap = 0; tap < 9; tap++) {
                int gy = y + tap / 3 - 1, gx = xx + tap % 3 - 1;
                xv[tap] = ((unsigned)gy < 64u && (unsigned)gx < 64u)
                          ? A.xp[((size_t)b * TT + A.t) * 4096 + gy * 64 + gx] : 0.f;
            }
        }
        #pragma unroll 1
        for (int jj = 0; jj < 8; jj++) {
            int col = chalf * 8 + jj;         // 0..15 local channel
            int co  = mt * 16 + col;
            int bb  = (b * 64 + co) * 4096 + pix;
            float cold = A.cbuf[bb];
            uint4 v = *(const uint4*)(A.wcb + (((size_t)co << 12) + pix) * 8);
            const __half2* hv = (const __half2*)&v;
            float2 wc01 = __half22float2(hv[0]);
            float2 wc23 = __half22float2(hv[1]);
            float2 bb01 = __half22float2(hv[2]);
            float2 bb23 = __half22float2(hv[3]);
            float pre[4];
            pre[0] = sE[(col * 4 + 0) * ESTR + pl] + wc01.x * cold + bb01.x;
            pre[1] = sE[(col * 4 + 1) * ESTR + pl] + wc01.y * cold + bb01.y;
            pre[2] = sE[(col * 4 + 2) * ESTR + pl] + wc23.x * cold + bb23.x;
            pre[3] = sE[(col * 4 + 3) * ESTR + pl] + wc23.y * cold + bb23.y;
            if (A.xp) {
                #pragma unroll
                for (int g = 0; g < 4; g++) {
                    const float* w9 = A.wx9 + (size_t)(g * 64 + co) * 9;
                    float s0 = 0.f;
                    #pragma unroll
                    for (int tap = 0; tap < 9; tap++) s0 += __ldg(w9 + tap) * xv[tap];
                    pre[g] += s0;
                }
            }
            float ig = sigf(pre[0]);
            float fg = sigf(pre[1]);
            float gg = tanhf_fast(pre[2]);
            float og = sigf(pre[3]);
            float cn = fg * cold + ig * gg;
            A.cbuf[bb] = cn;
            sH[pl * HSTR + col] = __float2half_rn(og * tanhf_fast(cn));
        }
    }
    __syncthreads();

    // copy-out: sH [256 px][16 ch] -> Tout. sH row stride 48B (16B-aligned).
    {
        int px = tid >> 1, q = tid & 1;
        int pix = y0 * 64 + px;
        int y = pix >> 6, x = pix & 63;
        __half* dst = A.Tout + (((size_t)b * TROW + (y + 1)) * TROW + (x + 1)) * 64
                      + mt * 16 + q * 8;
        *(uint4*)dst = *(const uint4*)(sH + px * HSTR + q * 8);
    }
}

// ---------------------------------------------------------------------------
// Final conv body: active CTAs mt==0 && nt<64 (512 px per CTA).
// ---------------------------------------------------------------------------
__device__ __forceinline__ void final_body(const CellArgs& A, char* smc)
{
    const int nt = blockIdx.x;
    const int mt = blockIdx.y;
    if (mt != 0 || nt >= 64) return;
    float* s_w = (float*)smc;   // 576 floats

    int tid = threadIdx.x;
    for (int i = tid; i < 576; i += 512) {
        int tap = i >> 6, c = i & 63;
        s_w[tap * 64 + c] = A.fw[c * 9 + tap];
    }
    __syncthreads();

    int b  = nt >> 3;
    int pb = nt & 7;
    int pix = pb * 512 + tid;
    int y = pix >> 6, x = pix & 63;
    float sum = A.fb[0];
    #pragma unroll
    for (int tap = 0; tap < 9; tap++) {
        int dy = tap / 3, dx = tap % 3;
        const __half* row =
            A.T0 + (((size_t)b * TROW + (y + dy)) * TROW + (x + dx)) * 64;
        const float* wt = s_w + tap * 64;
        #pragma unroll
        for (int c8 = 0; c8 < 8; c8++) {
            uint4 v = *(const uint4*)(row + c8 * 8);
            const __half* hv = (const __half*)&v;
            #pragma unroll
            for (int k = 0; k < 8; k++)
                sum += wt[c8 * 8 + k] * __half2float(hv[k]);
        }
    }
    A.cbuf[(size_t)b * (PRED * PIX) + A.t * PIX + pix] = sigf(sum);
}

// ---------------------------------------------------------------------------
// Fused dispatcher: grid (128, 4, nz). Slice z=0 runs `a`, z=1 runs `b`.
// ---------------------------------------------------------------------------
__global__ void __launch_bounds__(512, 2)
fused_kernel(CellArgs a, CellArgs b)
{
    extern __shared__ __align__(16) char smc[];
    if (blockIdx.z == 0) {
        if (a.kind == 0)      cell_body(a, smc);
        else if (a.kind == 1) final_body(a, smc);
    } else {
        if (b.kind == 0)      cell_body(b, smc);
        else if (b.kind == 1) final_body(b, smc);
    }
}

// ---------------------------------------------------------------------------
extern "C" void kernel_launch(void* const* d_in, const int* in_sizes, int n_in,
                              void* d_out, int out_size)
{
    const float* x    = (const float*)d_in[0];
    const float* e0Wx = (const float*)d_in[1];
    const float* e0Wh = (const float*)d_in[2];
    const float* e0Wc = (const float*)d_in[3];
    const float* e0b  = (const float*)d_in[4];
    const float* e1Wx = (const float*)d_in[5];
    const float* e1Wh = (const float*)d_in[6];
    const float* e1Wc = (const float*)d_in[7];
    const float* e1b  = (const float*)d_in[8];
    const float* d0Wx = (const float*)d_in[9];
    const float* d0Wh = (const float*)d_in[10];
    const float* d0Wc = (const float*)d_in[11];
    const float* d0b  = (const float*)d_in[12];
    const float* d1Wx = (const float*)d_in[13];
    const float* d1Wh = (const float*)d_in[14];
    const float* d1Wc = (const float*)d_in[15];
    const float* d1b  = (const float*)d_in[16];
    const float* finw = (const float*)d_in[17];
    const float* finb = (const float*)d_in[18];
    float* out = (float*)d_out;

    cudaFuncSetAttribute(fused_kernel,
                         cudaFuncAttributeMaxDynamicSharedMemorySize, SM_TOTAL);

    float* cbuf;
    __half *Tbuf, *Wbuf, *WBbuf;
    cudaGetSymbolAddress((void**)&cbuf, g_c);
    cudaGetSymbolAddress((void**)&Tbuf, g_T);
    cudaGetSymbolAddress((void**)&Wbuf, g_W);
    cudaGetSymbolAddress((void**)&WBbuf, g_WB);

    float* ec0 = cbuf + 0 * (size_t)NST;
    float* ec1 = cbuf + 1 * (size_t)NST;
    float* dc0 = cbuf + 2 * (size_t)NST;
    float* dc1 = cbuf + 3 * (size_t)NST;
    __half* Te0[2] = { Tbuf + 0 * TSZ, Tbuf + 1 * TSZ };
    __half* Te1[2] = { Tbuf + 2 * TSZ, Tbuf + 3 * TSZ };
    __half* Td0[2] = { Tbuf + 4 * TSZ, Tbuf + 5 * TSZ };
    __half* Td1[2] = { Tbuf + 6 * TSZ, Tbuf + 7 * TSZ };
    __half* W_e0h = Wbuf + 0 * (size_t)WSZ;
    __half* W_e1x = Wbuf + 1 * (size_t)WSZ;
    __half* W_e1h = Wbuf + 2 * (size_t)WSZ;
    __half* W_d0x = Wbuf + 3 * (size_t)WSZ;
    __half* W_d0h = Wbuf + 4 * (size_t)WSZ;
    __half* W_d1x = Wbuf + 5 * (size_t)WSZ;
    __half* W_d1h = Wbuf + 6 * (size_t)WSZ;
    __half* WB_e0 = WBbuf + 0 * (size_t)WBSZ;
    __half* WB_e1 = WBbuf + 1 * (size_t)WBSZ;
    __half* WB_d0 = WBbuf + 2 * (size_t)WBSZ;
    __half* WB_d1 = WBbuf + 3 * (size_t)WBSZ;

    {
        dim3 wgrid((WSZ + 255) / 256, 1, 7);
        wsplit_kernel<<<wgrid, 256>>>(e0Wh, e1Wx, e1Wh, d0Wx, d0Wh, d1Wx, d1Wh, Wbuf);
        dim3 pgrid((64 * 4096 + 255) / 256, 1, 4);
        wcpack_kernel<<<pgrid, 256>>>(e0Wc, e0b, e1Wc, e1b, d0Wc, d0b, d1Wc, d1b, WBbuf);
    }
    cudaMemsetAsync(cbuf, 0, (size_t)4 * NST * sizeof(float));
    cudaMemsetAsync(Tbuf, 0, (size_t)8 * TSZ * sizeof(__half));

    auto cellArgs = [&](const __half* T0, const __half* W0, const __half* T1,
                        const __half* W1, int nsrc, const __half* wcb,
                        float* cb, __half* To, const float* xp, const float* wx9, int t) {
        CellArgs a;
        a.T0 = T0; a.W0 = W0; a.T1 = T1; a.W1 = W1; a.nsrc = nsrc;
        a.wcb = wcb; a.fw = nullptr; a.fb = nullptr; a.cbuf = cb; a.Tout = To;
        a.xp = xp; a.wx9 = wx9; a.t = t; a.kind = 0;
        return a;
    };
    auto finalArgs = [&](const __half* T, int t) {
        CellArgs a;
        a.T0 = T; a.W0 = nullptr; a.T1 = nullptr; a.W1 = nullptr; a.nsrc = 0;
        a.wcb = nullptr; a.fw = finw; a.fb = finb; a.cbuf = out; a.Tout = nullptr;
        a.xp = nullptr; a.wx9 = nullptr; a.t = t; a.kind = 1;
        return a;
    };
    CellArgs none; none.kind = 2;
    none.T0 = none.T1 = nullptr; none.W0 = none.W1 = nullptr; none.nsrc = 0;
    none.wcb = nullptr; none.fw = none.fb = nullptr; none.cbuf = nullptr;
    none.Tout = nullptr; none.xp = none.wx9 = nullptr; none.t = 0;

    dim3 g1(128, 4, 1), g2(128, 4, 2), gf(64, 1, 1), blk(512);

    auto enc0 = [&](int t) {
        int r = t & 1, w = r ^ 1;
        return cellArgs(Te0[r], W_e0h, Te0[r], W_e0h, 1, WB_e0, ec0, Te0[w], x, e0Wx, t);
    };
    auto enc1 = [&](int t) {
        int r = t & 1, w = r ^ 1;
        return cellArgs(Te0[w], W_e1x, Te1[r], W_e1h, 2, WB_e1, ec1, Te1[w], nullptr, nullptr, 0);
    };
    auto dec0 = [&](int t) {
        int r = t & 1, w = r ^ 1;
        const __half* Ts = (t == 0) ? Te1[0] : Td1[r];
        return cellArgs(Ts, W_d0x, Td0[r], W_d0h, 2, WB_d0, dc0, Td0[w], nullptr, nullptr, 0);
    };
    auto dec1 = [&](int t) {
        int r = t & 1, w = r ^ 1;
        return cellArgs(Td0[w], W_d1x, Td1[r], W_d1h, 2, WB_d1, dc1, Td1[w], nullptr, nullptr, 0);
    };

    // ---- Encoder ----
    fused_kernel<<<g1, blk, SM_TOTAL>>>(enc0(0), none);
    for (int t = 0; t < TT - 1; t++)
        fused_kernel<<<g2, blk, SM_TOTAL>>>(enc1(t), enc0(t + 1));   // independent pair
    fused_kernel<<<g1, blk, SM_TOTAL>>>(enc1(TT - 1), none);
    // final encoder h1 in Te1[0] (t=9: w=0)

    // ---- Decoder ----
    fused_kernel<<<g1, blk, SM_TOTAL>>>(dec0(0), none);
    for (int t = 0; t < PRED; t++) {
        int w = (t & 1) ^ 1;
        fused_kernel<<<g1, blk, SM_TOTAL>>>(dec1(t), none);
        if (t < PRED - 1)
            fused_kernel<<<g2, blk, SM_TOTAL>>>(dec0(t + 1), finalArgs(Td1[w], t)); // read-read on Td1[w]
        else
            fused_kernel<<<gf, blk, SM_TOTAL>>>(finalArgs(Td1[w], t), none);
    }
}

// round 17
// speedup vs baseline: 1.0819x; 1.0819x over previous
#include <cuda_runtime.h>
#include <cuda_fp16.h>
#include <math.h>
#include <stdint.h>

// Problem constants
#define BB   8
#define TT   10
#define HH   64
#define WW   64
#define HID  64
#define PRED 10
#define PIX  (HH*WW)              // 4096
#define NST  (BB*HID*PIX)
#define TROW 66
#define TSZ  ((size_t)BB*TROW*TROW*HID)   // elems of one transposed fp16 tensor
#define WSZ  (9*256*64)           // fp16 weights per tensor (fragment-packed)
#define WBSZ (64*4096*8)          // packed Wc+bias per cell: [co][px][wc0..3,b0..3]

// ---------------------------------------------------------------------------
// Static scratch
// ---------------------------------------------------------------------------
__device__ float g_c[4][NST];                                   // c states
__device__ __align__(16) __half g_T[4][2 * BB*TROW*TROW*HID];   // h, ping-pong
__device__ __align__(16) __half g_W[7][WSZ];                    // A-fragment layout
__device__ __align__(16) __half g_WB[4][WBSZ];                  // packed Wc|bias

// ---------------------------------------------------------------------------
// Weight transform: w (256,64,3,3) -> mma A-fragment layout:
//   [tap][g16 (m/16)][ks (k/16)][lane][4xu32]  (16B per lane, LDG.128 ready)
// m-row index = co*4 + gate (gates of a channel adjacent).
// Fragment map (m16n8k16 A): j-th u32 of lane holds halves
//   row = g16*16 + (lane>>2) + (j&1)*8
//   col = ks*16 + (lane&3)*2 + (j>>1)*8 + {0,1}
// ---------------------------------------------------------------------------
__global__ void wsplit_kernel(const float* w0, const float* w1, const float* w2,
                              const float* w3, const float* w4, const float* w5,
                              const float* w6, __half* __restrict__ wt_base)
{
    int i = blockIdx.x * blockDim.x + threadIdx.x;   // over WSZ halves
    if (i >= WSZ) return;
    int z = blockIdx.z;
    const float* w;
    switch (z) {
        case 0: w = w0; break;  case 1: w = w1; break;
        case 2: w = w2; break;  case 3: w = w3; break;
        case 4: w = w4; break;  case 5: w = w5; break;
        default: w = w6; break;
    }
    __half* wt = wt_base + (size_t)z * WSZ;

    int tap  = i / 16384;
    int idx  = i - tap * 16384;
    int jj   = idx & 7;          // half within lane's 16B
    int lane = (idx >> 3) & 31;
    int ks   = (idx >> 8) & 3;
    int g16  = idx >> 10;        // 0..15
    int j      = jj >> 1;
    int which  = jj & 1;
    int row = g16 * 16 + (lane >> 2) + (j & 1) * 8;       // m index (co*4+gate)
    int col = ks * 16 + (lane & 3) * 2 + (j >> 1) * 8 + which;
    int co = row >> 2, gate = row & 3;
    wt[i] = __float2half_rn(w[((gate * 64 + co) * 64 + col) * 9 + tap]);
}

// ---------------------------------------------------------------------------
// Pack Wc + bias -> [co][px][wc0..3,b0..3] fp16 (one LDG.128 in epilogue)
// ---------------------------------------------------------------------------
__global__ void wcpack_kernel(const float* wc0, const float* b0,
                              const float* wc1, const float* b1,
                              const float* wc2, const float* b2,
                              const float* wc3, const float* b3,
                              __half* __restrict__ out_base)
{
    int i = blockIdx.x * blockDim.x + threadIdx.x;   // over 64*4096
    if (i >= 64 * 4096) return;
    int z = blockIdx.z;
    const float *wc, *bi;
    switch (z) {
        case 0: wc = wc0; bi = b0; break;
        case 1: wc = wc1; bi = b1; break;
        case 2: wc = wc2; bi = b2; break;
        default: wc = wc3; bi = b3; break;
    }
    __half* out = out_base + (size_t)z * WBSZ;
    int px = i & 4095;
    int co = i >> 12;
    __half* dst = out + (size_t)i * 8;
    #pragma unroll
    for (int g = 0; g < 4; g++) {
        dst[g]     = __float2half_rn(wc[(g * 64 + co) * 4096 + px]);
        dst[4 + g] = __float2half_rn(bi[(g * 64 + co) * 4096 + px]);
    }
}

// ---------------------------------------------------------------------------
// low-level helpers
// ---------------------------------------------------------------------------
__device__ __forceinline__ uint32_t smem_u32(const void* p) {
    uint32_t a;
    asm("{ .reg .u64 t; cvta.to.shared.u64 t, %1; cvt.u32.u64 %0, t; }" : "=r"(a) : "l"(p));
    return a;
}
__device__ __forceinline__ void cp16(uint32_t dst, const void* src) {
    asm volatile("cp.async.cg.shared.global [%0], [%1], 16;" :: "r"(dst), "l"(src));
}
#define CP_COMMIT() asm volatile("cp.async.commit_group;" ::: "memory")
#define CP_WAIT0()  asm volatile("cp.async.wait_group 0;" ::: "memory")

__device__ __forceinline__ void ldm_x4(unsigned* r, uint32_t addr) {
    asm volatile("ldmatrix.sync.aligned.m8n8.x4.shared.b16 {%0,%1,%2,%3}, [%4];"
        : "=r"(r[0]), "=r"(r[1]), "=r"(r[2]), "=r"(r[3]) : "r"(addr));
}
__device__ __forceinline__ void mma16816(float* d, const unsigned* a,
                                         unsigned b0, unsigned b1)
{
    asm("mma.sync.aligned.m16n8k16.row.col.f32.f16.f16.f32 "
        "{%0,%1,%2,%3}, {%4,%5,%6,%7}, {%8,%9}, {%0,%1,%2,%3};"
        : "+f"(d[0]), "+f"(d[1]), "+f"(d[2]), "+f"(d[3])
        : "r"(a[0]), "r"(a[1]), "r"(a[2]), "r"(a[3]), "r"(b0), "r"(b1));
}

// Fast activations (EX2/RCP)
__device__ __forceinline__ float ex2f(float x) {
    float r; asm("ex2.approx.f32 %0, %1;" : "=f"(r) : "f"(x)); return r;
}
__device__ __forceinline__ float rcpf(float x) {
    float r; asm("rcp.approx.f32 %0, %1;" : "=f"(r) : "f"(x)); return r;
}
#define LOG2E 1.4426950408889634f
__device__ __forceinline__ float sigf(float v) {
    return rcpf(1.f + ex2f(-v * LOG2E));
}
__device__ __forceinline__ float tanhf_fast(float v) {
    return 1.f - 2.f * rcpf(1.f + ex2f(2.f * LOG2E * v));
}

// SMEM layout (bytes), 256-thread CTA, 4 CTAs/SM:
//   B tile : 264 rows x 144B = 38016   [0 .. 38016)
//   sE (64 gate-rows x 136 f32 = 34816) overlays B after mma
//   sH (128 px x 24 fp16 = 6144)       [38016 .. 44160)
#define SB_OFF   0
#define SH_OFF   38016
#define SM_TOTAL 44160
#define ESTR     136
#define HSTR     24

// ---------------------------------------------------------------------------
// Work descriptor
// ---------------------------------------------------------------------------
struct CellArgs {
    const __half* T0;
    const __half* W0;
    const __half* T1;
    const __half* W1;
    int nsrc;
    const __half* wcb;
    const float*  fw;
    const float*  fb;
    float*        cbuf;
    __half*       Tout;
    const float*  xp;
    const float*  wx9;
    int t;
    int kind;           // 0 = cell, 1 = final conv, 2 = none
};

// ---------------------------------------------------------------------------
// Cell body. CTA: M=64 gate-rows (mt 0..3 -> channels mt*16..mt*16+15),
// N=128 px (2 image rows of one batch). 8 warps: wm {0,1} x wn {0..3};
// warp tile 32m x 32n. 4 CTAs/SM. Weights: fragment-layout LDG (no smem,
// no per-tap barriers — 2 barriers per cell in the mainloop).
// ---------------------------------------------------------------------------
__device__ __forceinline__ void cell_body(const CellArgs& A, char* smc)
{
    const uint32_t smb = smem_u32(smc);
    float*  sE = (float*)smc;
    __half* sH = (__half*)(smc + SH_OFF);

    const int tid  = threadIdx.x;
    const int lane = tid & 31;
    const int warp = tid >> 5;
    const int wm   = warp >> 2;      // 0..1 (m half: wm*32)
    const int wn   = warp & 3;       // 0..3
    const int nt   = blockIdx.x;     // 0..255
    const int mt   = blockIdx.y;     // 0..3
    const int b    = nt >> 5;
    const int y0   = (nt & 31) << 1; // first of 2 image rows

    const int b_row_l = (lane & 7) + ((lane >> 4) << 3);
    const int b_col_l = ((lane >> 3) & 1) * 8;

    float acc[2][4][4];
    #pragma unroll
    for (int mi = 0; mi < 2; mi++)
        #pragma unroll
        for (int ni = 0; ni < 4; ni++)
            #pragma unroll
            for (int r = 0; r < 4; r++) acc[mi][ni][r] = 0.f;

    for (int s = 0; s < A.nsrc; s++) {
        const __half* T = s ? A.T1 : A.T0;
        const uint4* Wf = (const uint4*)(s ? A.W1 : A.W0);

        __syncthreads();   // prior source's mma reads of B done
        // fill B: 264 padded rows x 8 vec16
        for (int i = tid; i < 2112; i += 256) {
            int p = i >> 3, v = i & 7;
            int r = p / TROW, px = p - r * TROW;
            const __half* src =
                T + (((size_t)b * TROW + (y0 + r)) * TROW + px) * 64 + v * 8;
            cp16(smb + SB_OFF + p * 144 + v * 16, src);
        }
        CP_COMMIT();
        CP_WAIT0();
        __syncthreads();   // B visible to all warps

        // barrier-free tap loop: A fragments via LDG.128 (broadcast-friendly)
        for (int tap = 0; tap < 9; tap++) {
            const int dy = tap / 3, dx = tap - dy * 3;
            const int ylocal = wn >> 1, xlocal = (wn & 1) * 32;
            const int prow_base = (ylocal + dy) * TROW + xlocal + dx;
            const uint32_t bBase = smb + SB_OFF;
            // A fragment base for this warp's two 16-row groups
            const int g16_0 = mt * 4 + wm * 2;

            #pragma unroll
            for (int ks = 0; ks < 4; ks++) {
                unsigned bfr[2][4];
                #pragma unroll
                for (int p2 = 0; p2 < 2; p2++)
                    ldm_x4(bfr[p2], bBase + (prow_base + p2 * 16 + b_row_l) * 144
                                          + (ks * 16 + b_col_l) * 2);
                unsigned afr[2][4];
                #pragma unroll
                for (int mi = 0; mi < 2; mi++) {
                    uint4 v = __ldg(Wf + (((tap * 16 + g16_0 + mi) * 4 + ks) * 32) + lane);
                    afr[mi][0] = v.x; afr[mi][1] = v.y;
                    afr[mi][2] = v.z; afr[mi][3] = v.w;
                }
                #pragma unroll
                for (int p2 = 0; p2 < 2; p2++)
                    #pragma unroll
                    for (int mi = 0; mi < 2; mi++) {
                        mma16816(acc[mi][2 * p2],     afr[mi], bfr[p2][0], bfr[p2][1]);
                        mma16816(acc[mi][2 * p2 + 1], afr[mi], bfr[p2][2], bfr[p2][3]);
                    }
            }
        }
    }

    // ---- epilogue (sE overlays B region; mma is done) ----
    __syncthreads();
    const int gr = lane >> 2, ci = lane & 3;
    #pragma unroll
    for (int mi = 0; mi < 2; mi++)
        #pragma unroll
        for (int ni = 0; ni < 4; ni++) {
            int r0 = wm * 32 + mi * 16 + gr;
            int n  = wn * 32 + ni * 8 + 2 * ci;
            *(float2*)(sE + r0 * ESTR + n)       = make_float2(acc[mi][ni][0], acc[mi][ni][1]);
            *(float2*)(sE + (r0 + 8) * ESTR + n) = make_float2(acc[mi][ni][2], acc[mi][ni][3]);
        }
    __syncthreads();

    #pragma unroll 1
    for (int ii = 0; ii < 4; ii++) {
        int pl  = lane + 32 * ii;            // 0..127
        int pix = y0 * 64 + pl;
        float xv[9];
        if (A.xp) {
            int y = pix >> 6, xx = pix & 63;
            #pragma unroll
            for (int tap = 0; tap < 9; tap++) {
                int gy = y + tap / 3 - 1, gx = xx + tap % 3 - 1;
                xv[tap] = ((unsigned)gy < 64u && (unsigned)gx < 64u)
                          ? A.xp[((size_t)b * TT + A.t) * 4096 + gy * 64 + gx] : 0.f;
            }
        }
        #pragma unroll 1
        for (int jj = 0; jj < 2; jj++) {
            int col = warp + 8 * jj;          // 0..15 local channel
            int co  = mt * 16 + col;
            int bb  = (b * 64 + co) * 4096 + pix;
            float cold = A.cbuf[bb];
            uint4 v = *(const uint4*)(A.wcb + (((size_t)co << 12) + pix) * 8);
            const __half2* hv = (const __half2*)&v;
            float2 wc01 = __half22float2(hv[0]);
            float2 wc23 = __half22float2(hv[1]);
            float2 bb01 = __half22float2(hv[2]);
            float2 bb23 = __half22float2(hv[3]);
            float pre[4];
            pre[0] = sE[(col * 4 + 0) * ESTR + pl] + wc01.x * cold + bb01.x;
            pre[1] = sE[(col * 4 + 1) * ESTR + pl] + wc01.y * cold + bb01.y;
            pre[2] = sE[(col * 4 + 2) * ESTR + pl] + wc23.x * cold + bb23.x;
            pre[3] = sE[(col * 4 + 3) * ESTR + pl] + wc23.y * cold + bb23.y;
            if (A.xp) {
                #pragma unroll
                for (int g = 0; g < 4; g++) {
                    const float* w9 = A.wx9 + (size_t)(g * 64 + co) * 9;
                    float s0 = 0.f;
                    #pragma unroll
                    for (int tap = 0; tap < 9; tap++) s0 += __ldg(w9 + tap) * xv[tap];
                    pre[g] += s0;
                }
            }
            float ig = sigf(pre[0]);
            float fg = sigf(pre[1]);
            float gg = tanhf_fast(pre[2]);
            float og = sigf(pre[3]);
            float cn = fg * cold + ig * gg;
            A.cbuf[bb] = cn;
            sH[pl * HSTR + col] = __float2half_rn(og * tanhf_fast(cn));
        }
    }
    __syncthreads();

    // copy-out: sH [128 px][16 ch] -> Tout. sH row stride 48B (16B-aligned).
    for (int i = tid; i < 256; i += 256) {
        int px = i >> 1, q = i & 1;
        int pix = y0 * 64 + px;
        int y = pix >> 6, x = pix & 63;
        __half* dst = A.Tout + (((size_t)b * TROW + (y + 1)) * TROW + (x + 1)) * 64
                      + mt * 16 + q * 8;
        *(uint4*)dst = *(const uint4*)(sH + px * HSTR + q * 8);
    }
}

// ---------------------------------------------------------------------------
// Final conv body: active CTAs mt==0 && nt<128.
// ---------------------------------------------------------------------------
__device__ __forceinline__ void final_body(const CellArgs& A, char* smc)
{
    const int nt = blockIdx.x;
    const int mt = blockIdx.y;
    if (mt != 0 || nt >= 128) return;
    float* s_w = (float*)smc;   // 576 floats

    int tid = threadIdx.x;
    for (int i = tid; i < 576; i += 256) {
        int tap = i >> 6, c = i & 63;
        s_w[tap * 64 + c] = A.fw[c * 9 + tap];
    }
    __syncthreads();

    int b  = nt >> 4;
    int pb = nt & 15;
    int pix = pb * 256 + tid;
    int y = pix >> 6, x = pix & 63;
    float sum = A.fb[0];
    #pragma unroll
    for (int tap = 0; tap < 9; tap++) {
        int dy = tap / 3, dx = tap % 3;
        const __half* row =
            A.T0 + (((size_t)b * TROW + (y + dy)) * TROW + (x + dx)) * 64;
        const float* wt = s_w + tap * 64;
        #pragma unroll
        for (int c8 = 0; c8 < 8; c8++) {
            uint4 v = *(const uint4*)(row + c8 * 8);
            const __half* hv = (const __half*)&v;
            #pragma unroll
            for (int k = 0; k < 8; k++)
                sum += wt[c8 * 8 + k] * __half2float(hv[k]);
        }
    }
    A.cbuf[(size_t)b * (PRED * PIX) + A.t * PIX + pix] = sigf(sum);
}

// ---------------------------------------------------------------------------
// Fused dispatcher: grid (256, 4, nz). Slice z=0 runs `a`, z=1 runs `b`.
// ---------------------------------------------------------------------------
__global__ void __launch_bounds__(256, 4)
fused_kernel(CellArgs a, CellArgs b)
{
    extern __shared__ __align__(16) char smc[];
    if (blockIdx.z == 0) {
        if (a.kind == 0)      cell_body(a, smc);
        else if (a.kind == 1) final_body(a, smc);
    } else {
        if (b.kind == 0)      cell_body(b, smc);
        else if (b.kind == 1) final_body(b, smc);
    }
}

// ---------------------------------------------------------------------------
extern "C" void kernel_launch(void* const* d_in, const int* in_sizes, int n_in,
                              void* d_out, int out_size)
{
    const float* x    = (const float*)d_in[0];
    const float* e0Wx = (const float*)d_in[1];
    const float* e0Wh = (const float*)d_in[2];
    const float* e0Wc = (const float*)d_in[3];
    const float* e0b  = (const float*)d_in[4];
    const float* e1Wx = (const float*)d_in[5];
    const float* e1Wh = (const float*)d_in[6];
    const float* e1Wc = (const float*)d_in[7];
    const float* e1b  = (const float*)d_in[8];
    const float* d0Wx = (const float*)d_in[9];
    const float* d0Wh = (const float*)d_in[10];
    const float* d0Wc = (const float*)d_in[11];
    const float* d0b  = (const float*)d_in[12];
    const float* d1Wx = (const float*)d_in[13];
    const float* d1Wh = (const float*)d_in[14];
    const float* d1Wc = (const float*)d_in[15];
    const float* d1b  = (const float*)d_in[16];
    const float* finw = (const float*)d_in[17];
    const float* finb = (const float*)d_in[18];
    float* out = (float*)d_out;

    cudaFuncSetAttribute(fused_kernel,
                         cudaFuncAttributeMaxDynamicSharedMemorySize, SM_TOTAL);

    float* cbuf;
    __half *Tbuf, *Wbuf, *WBbuf;
    cudaGetSymbolAddress((void**)&cbuf, g_c);
    cudaGetSymbolAddress((void**)&Tbuf, g_T);
    cudaGetSymbolAddress((void**)&Wbuf, g_W);
    cudaGetSymbolAddress((void**)&WBbuf, g_WB);

    float* ec0 = cbuf + 0 * (size_t)NST;
    float* ec1 = cbuf + 1 * (size_t)NST;
    float* dc0 = cbuf + 2 * (size_t)NST;
    float* dc1 = cbuf + 3 * (size_t)NST;
    __half* Te0[2] = { Tbuf + 0 * TSZ, Tbuf + 1 * TSZ };
    __half* Te1[2] = { Tbuf + 2 * TSZ, Tbuf + 3 * TSZ };
    __half* Td0[2] = { Tbuf + 4 * TSZ, Tbuf + 5 * TSZ };
    __half* Td1[2] = { Tbuf + 6 * TSZ, Tbuf + 7 * TSZ };
    __half* W_e0h = Wbuf + 0 * (size_t)WSZ;
    __half* W_e1x = Wbuf + 1 * (size_t)WSZ;
    __half* W_e1h = Wbuf + 2 * (size_t)WSZ;
    __half* W_d0x = Wbuf + 3 * (size_t)WSZ;
    __half* W_d0h = Wbuf + 4 * (size_t)WSZ;
    __half* W_d1x = Wbuf + 5 * (size_t)WSZ;
    __half* W_d1h = Wbuf + 6 * (size_t)WSZ;
    __half* WB_e0 = WBbuf + 0 * (size_t)WBSZ;
    __half* WB_e1 = WBbuf + 1 * (size_t)WBSZ;
    __half* WB_d0 = WBbuf + 2 * (size_t)WBSZ;
    __half* WB_d1 = WBbuf + 3 * (size_t)WBSZ;

    {
        dim3 wgrid((WSZ + 255) / 256, 1, 7);
        wsplit_kernel<<<wgrid, 256>>>(e0Wh, e1Wx, e1Wh, d0Wx, d0Wh, d1Wx, d1Wh, Wbuf);
        dim3 pgrid((64 * 4096 + 255) / 256, 1, 4);
        wcpack_kernel<<<pgrid, 256>>>(e0Wc, e0b, e1Wc, e1b, d0Wc, d0b, d1Wc, d1b, WBbuf);
    }
    cudaMemsetAsync(cbuf, 0, (size_t)4 * NST * sizeof(float));
    cudaMemsetAsync(Tbuf, 0, (size_t)8 * TSZ * sizeof(__half));

    auto cellArgs = [&](const __half* T0, const __half* W0, const __half* T1,
                        const __half* W1, int nsrc, const __half* wcb,
                        float* cb, __half* To, const float* xp, const float* wx9, int t) {
        CellArgs a;
        a.T0 = T0; a.W0 = W0; a.T1 = T1; a.W1 = W1; a.nsrc = nsrc;
        a.wcb = wcb; a.fw = nullptr; a.fb = nullptr; a.cbuf = cb; a.Tout = To;
        a.xp = xp; a.wx9 = wx9; a.t = t; a.kind = 0;
        return a;
    };
    auto finalArgs = [&](const __half* T, int t) {
        CellArgs a;
        a.T0 = T; a.W0 = nullptr; a.T1 = nullptr; a.W1 = nullptr; a.nsrc = 0;
        a.wcb = nullptr; a.fw = finw; a.fb = finb; a.cbuf = out; a.Tout = nullptr;
        a.xp = nullptr; a.wx9 = nullptr; a.t = t; a.kind = 1;
        return a;
    };
    CellArgs none; none.kind = 2;
    none.T0 = none.T1 = nullptr; none.W0 = none.W1 = nullptr; none.nsrc = 0;
    none.wcb = nullptr; none.fw = none.fb = nullptr; none.cbuf = nullptr;
    none.Tout = nullptr; none.xp = none.wx9 = nullptr; none.t = 0;

    dim3 g1(256, 4, 1), g2(256, 4, 2), gf(128, 1, 1), blk(256);

    auto enc0 = [&](int t) {
        int r = t & 1, w = r ^ 1;
        return cellArgs(Te0[r], W_e0h, Te0[r], W_e0h, 1, WB_e0, ec0, Te0[w], x, e0Wx, t);
    };
    auto enc1 = [&](int t) {
        int r = t & 1, w = r ^ 1;
        return cellArgs(Te0[w], W_e1x, Te1[r], W_e1h, 2, WB_e1, ec1, Te1[w], nullptr, nullptr, 0);
    };
    auto dec0 = [&](int t) {
        int r = t & 1, w = r ^ 1;
        const __half* Ts = (t == 0) ? Te1[0] : Td1[r];
        return cellArgs(Ts, W_d0x, Td0[r], W_d0h, 2, WB_d0, dc0, Td0[w], nullptr, nullptr, 0);
    };
    auto dec1 = [&](int t) {
        int r = t & 1, w = r ^ 1;
        return cellArgs(Td0[w], W_d1x, Td1[r], W_d1h, 2, WB_d1, dc1, Td1[w], nullptr, nullptr, 0);
    };

    // ---- Encoder ----
    fused_kernel<<<g1, blk, SM_TOTAL>>>(enc0(0), none);
    for (int t = 0; t < TT - 1; t++)
        fused_kernel<<<g2, blk, SM_TOTAL>>>(enc1(t), enc0(t + 1));   // independent pair
    fused_kernel<<<g1, blk, SM_TOTAL>>>(enc1(TT - 1), none);
    // final encoder h1 in Te1[0] (t=9: w=0)

    // ---- Decoder ----
    fused_kernel<<<g1, blk, SM_TOTAL>>>(dec0(0), none);
    for (int t = 0; t < PRED; t++) {
        int w = (t & 1) ^ 1;
        fused_kernel<<<g1, blk, SM_TOTAL>>>(dec1(t), none);
        if (t < PRED - 1)
            fused_kernel<<<g2, blk, SM_TOTAL>>>(dec0(t + 1), finalArgs(Td1[w], t)); // read-read on Td1[w]
        else
            fused_kernel<<<gf, blk, SM_TOTAL>>>(finalArgs(Td1[w], t), none);
    }
}